// round 1
// baseline (speedup 1.0000x reference)
#include <cuda_runtime.h>
#include <cuda_bf16.h>
#include <math.h>

#define BSZ   512
#define TT    64          // xin timesteps (x has 65, last is target)
#define NF    512         // feature dim
#define HID   1000
#define MAXG  16
#define EPSV  1e-5f
#define BF    (BSZ*NF)    // 262144

// ---------------- scratch (static device memory; no allocation allowed) ----
__device__ float g_xint[TT*BSZ*NF];     // xin transposed to (T,B,F)
__device__ float g_u   [TT*BSZ*NF];     // x@W_ih^T + b_ih, (T,B,F)
__device__ float g_hs  [TT*BSZ*NF];     // hidden states, (T,B,F)
__device__ float g_z1  [TT*BSZ*HID];
__device__ float g_z2  [TT*BSZ*HID];
__device__ float g_y   [TT*BSZ*NF];     // autoenc output over all rows
__device__ float g_xall[MAXG*BSZ*NF];   // decoder outputs per gap
__device__ float g_ud  [BSZ*NF];
__device__ float g_hd  [2*BSZ*NF];
__device__ float g_dz1 [BSZ*HID];
__device__ float g_dz2 [BSZ*HID];
__device__ float g_a1[HID], g_d1[HID];
__device__ float g_a2[HID], g_d2[HID];
__device__ float g_a3[NF],  g_d3[NF];
__device__ double g_sum1, g_sum2;

// ---------------- prep: transpose xin, fold BN, zero sums -------------------
__global__ void prep_kernel(const float* __restrict__ x,
    const float* b1, const float* g1, const float* be1, const float* rm1, const float* rv1,
    const float* b2, const float* g2, const float* be2, const float* rm2, const float* rv2,
    const float* b3, const float* g3, const float* be3, const float* rm3, const float* rv3)
{
    long long idx = (long long)blockIdx.x * blockDim.x + threadIdx.x;
    const long long TOT = (long long)TT * BSZ * NF;
    if (idx < TOT) {
        int f = (int)(idx % NF);
        long long tb = idx / NF;
        int b = (int)(tb % BSZ);
        int t = (int)(tb / BSZ);
        // g_xint[(t,b,f)] = x[b, t, f]
        g_xint[idx] = x[((long long)b * (TT + 1) + t) * NF + f];
    }
    if (idx < HID) {
        float s1 = g1[idx] / sqrtf(rv1[idx] + EPSV);
        g_a1[idx] = s1;
        g_d1[idx] = s1 * (b1[idx] - rm1[idx]) + be1[idx];
        float s2 = g2[idx] / sqrtf(rv2[idx] + EPSV);
        g_a2[idx] = s2;
        g_d2[idx] = s2 * (b2[idx] - rm2[idx]) + be2[idx];
    }
    if (idx < NF) {
        float s3 = g3[idx] / sqrtf(rv3[idx] + EPSV);
        g_a3[idx] = s3;
        g_d3[idx] = s3 * (b3[idx] - rm3[idx]) + be3[idx];
    }
    if (idx == 0) { g_sum1 = 0.0; g_sum2 = 0.0; }
}

// ---------------- h1 = tanh(U0 + b_hh) (h0 = 0) -----------------------------
__global__ void step0_kernel(const float* __restrict__ bhh)
{
    int idx = blockIdx.x * blockDim.x + threadIdx.x;
    if (idx < BF) {
        int f = idx & (NF - 1);
        g_hs[idx] = tanhf(g_u[idx] + bhh[f]);
    }
}

// ---------------- tiled SGEMM: C[M,N] = act((A[M,K] @ W[N,K]^T)*s + d (+U)) --
// BM=BN=64, BK=16, 256 threads, 4x4 per-thread tile. M must be mult of 64.
#define GBM 64
#define GBN 64
#define GBK 16

template<bool HAS_SCALE, bool HAS_U, bool DO_TANH>
__global__ void gemm_kernel(const float* __restrict__ A, const float* __restrict__ W,
                            const float* __restrict__ bias, const float* __restrict__ scale,
                            const float* __restrict__ Uadd, float* __restrict__ C,
                            int M, int N, int K)
{
    __shared__ float sA[GBM][GBK + 1];
    __shared__ float sW[GBN][GBK + 1];

    const int tx = threadIdx.x & 15;      // 0..15 -> n
    const int ty = threadIdx.x >> 4;      // 0..15 -> m
    const int m0 = blockIdx.y * GBM;
    const int n0 = blockIdx.x * GBN;

    float acc[4][4] = {};

    for (int kk = 0; kk < K; kk += GBK) {
        #pragma unroll
        for (int l = 0; l < 4; l++) {
            int e = threadIdx.x + l * 256;
            int r = e >> 4, c = e & 15;
            int gk = kk + c;
            sA[r][c] = (gk < K) ? A[(long long)(m0 + r) * K + gk] : 0.0f;
        }
        #pragma unroll
        for (int l = 0; l < 4; l++) {
            int e = threadIdx.x + l * 256;
            int r = e >> 4, c = e & 15;
            int gk = kk + c;
            int gn = n0 + r;
            sW[r][c] = (gn < N && gk < K) ? W[(long long)gn * K + gk] : 0.0f;
        }
        __syncthreads();

        #pragma unroll
        for (int k = 0; k < GBK; k++) {
            float ra[4], rw[4];
            #pragma unroll
            for (int i = 0; i < 4; i++) ra[i] = sA[ty * 4 + i][k];
            #pragma unroll
            for (int j = 0; j < 4; j++) rw[j] = sW[tx * 4 + j][k];
            #pragma unroll
            for (int i = 0; i < 4; i++)
                #pragma unroll
                for (int j = 0; j < 4; j++)
                    acc[i][j] += ra[i] * rw[j];
        }
        __syncthreads();
    }

    #pragma unroll
    for (int i = 0; i < 4; i++) {
        int m = m0 + ty * 4 + i;
        #pragma unroll
        for (int j = 0; j < 4; j++) {
            int n = n0 + tx * 4 + j;
            if (n < N) {
                float v = acc[i][j];
                if (HAS_SCALE) v = v * scale[n] + bias[n];
                else           v += bias[n];
                if (HAS_U)     v += Uadd[(long long)m * N + n];
                if (DO_TANH)   v = tanhf(v);
                C[(long long)m * N + n] = v;
            }
        }
    }
}

// ---------------- reductions -------------------------------------------------
__device__ __forceinline__ double block_reduce(double v)
{
    __shared__ double sh[32];
    #pragma unroll
    for (int o = 16; o > 0; o >>= 1) v += __shfl_down_sync(0xffffffffu, v, o);
    int lane = threadIdx.x & 31, w = threadIdx.x >> 5;
    if (lane == 0) sh[w] = v;
    __syncthreads();
    if (w == 0) {
        int nw = (blockDim.x + 31) >> 5;
        v = (lane < nw) ? sh[lane] : 0.0;
        #pragma unroll
        for (int o = 16; o > 0; o >>= 1) v += __shfl_down_sync(0xffffffffu, v, o);
    }
    return v;
}

// sum over (T-1)*B*F of (Y[t,b,f] - XIN[t+1,b,f])^2  (linear offset trick)
__global__ void loss1_kernel()
{
    const long long TOT = (long long)(TT - 1) * BSZ * NF;
    double local = 0.0;
    for (long long idx = (long long)blockIdx.x * blockDim.x + threadIdx.x;
         idx < TOT; idx += (long long)gridDim.x * blockDim.x) {
        float d = g_y[idx] - g_xint[idx + BF];
        local += (double)d * (double)d;
    }
    double s = block_reduce(local);
    if (threadIdx.x == 0) atomicAdd(&g_sum1, s);
}

// gather x_pred per batch row, write to out, accumulate sum2
__global__ void finalize_kernel(const float* __restrict__ x,
                                const int* __restrict__ t,
                                float* __restrict__ out)
{
    int b = blockIdx.x;
    int g = t[b] - 1;                               // 0..15
    const float* xp = g_xall + ((long long)g * BSZ + b) * NF;
    const float* xf = x + ((long long)b * (TT + 1) + TT) * NF;  // x[b, 64, :]
    double local = 0.0;
    for (int f = threadIdx.x; f < NF; f += blockDim.x) {
        float v = xp[f];
        out[(long long)b * NF + f] = v;
        float d = v - xf[f];
        local += (double)d * (double)d;
    }
    double s = block_reduce(local);
    if (threadIdx.x == 0) atomicAdd(&g_sum2, s);
}

__global__ void write_loss_kernel(float* __restrict__ out, int out_size)
{
    if (out_size > BSZ * NF) {
        double n1 = (double)(TT - 1) * BSZ * NF;    // 63*512*512
        double n2 = (double)BSZ * NF;
        double loss = g_sum1 / (n1 * n1) + g_sum2 / (n2 * n2);
        out[BSZ * NF] = (float)loss;
    }
}

// ---------------- launch -----------------------------------------------------
extern "C" void kernel_launch(void* const* d_in, const int* in_sizes, int n_in,
                              void* d_out, int out_size)
{
    const float* x    = (const float*)d_in[0];
    const int*   t    = (const int*)  d_in[1];
    const float* W_ih = (const float*)d_in[2];
    const float* W_hh = (const float*)d_in[3];
    const float* b_ih = (const float*)d_in[4];
    const float* b_hh = (const float*)d_in[5];
    const float* W1   = (const float*)d_in[6];
    const float* b1   = (const float*)d_in[7];
    const float* g1   = (const float*)d_in[8];
    const float* be1  = (const float*)d_in[9];
    const float* rm1  = (const float*)d_in[10];
    const float* rv1  = (const float*)d_in[11];
    const float* W2   = (const float*)d_in[12];
    const float* b2   = (const float*)d_in[13];
    const float* g2   = (const float*)d_in[14];
    const float* be2  = (const float*)d_in[15];
    const float* rm2  = (const float*)d_in[16];
    const float* rv2  = (const float*)d_in[17];
    const float* W3   = (const float*)d_in[18];
    const float* b3   = (const float*)d_in[19];
    const float* g3   = (const float*)d_in[20];
    const float* be3  = (const float*)d_in[21];
    const float* rm3  = (const float*)d_in[22];
    const float* rv3  = (const float*)d_in[23];
    float* out = (float*)d_out;

    float *xint, *u, *hs, *z1, *z2, *y, *xall, *ud, *hd, *dz1, *dz2;
    float *a1, *d1, *a2, *d2, *a3, *d3;
    cudaGetSymbolAddress((void**)&xint, g_xint);
    cudaGetSymbolAddress((void**)&u,    g_u);
    cudaGetSymbolAddress((void**)&hs,   g_hs);
    cudaGetSymbolAddress((void**)&z1,   g_z1);
    cudaGetSymbolAddress((void**)&z2,   g_z2);
    cudaGetSymbolAddress((void**)&y,    g_y);
    cudaGetSymbolAddress((void**)&xall, g_xall);
    cudaGetSymbolAddress((void**)&ud,   g_ud);
    cudaGetSymbolAddress((void**)&hd,   g_hd);
    cudaGetSymbolAddress((void**)&dz1,  g_dz1);
    cudaGetSymbolAddress((void**)&dz2,  g_dz2);
    cudaGetSymbolAddress((void**)&a1,   g_a1);
    cudaGetSymbolAddress((void**)&d1,   g_d1);
    cudaGetSymbolAddress((void**)&a2,   g_a2);
    cudaGetSymbolAddress((void**)&d2,   g_d2);
    cudaGetSymbolAddress((void**)&a3,   g_a3);
    cudaGetSymbolAddress((void**)&d3,   g_d3);

    const long long TOT = (long long)TT * BSZ * NF;
    prep_kernel<<<(unsigned)((TOT + 255) / 256), 256>>>(
        x, b1, g1, be1, rm1, rv1, b2, g2, be2, rm2, rv2, b3, g3, be3, rm3, rv3);

    // U = XIN @ W_ih^T + b_ih  over all T*B rows
    {
        dim3 grid(NF / GBN, (TT * BSZ) / GBM);
        gemm_kernel<false, false, false><<<grid, 256>>>(
            xint, W_ih, b_ih, nullptr, nullptr, u, TT * BSZ, NF, NF);
    }

    // scan
    step0_kernel<<<(BF + 255) / 256, 256>>>(b_hh);
    {
        dim3 grid(NF / GBN, BSZ / GBM);
        for (int st = 1; st < TT; st++) {
            gemm_kernel<false, true, true><<<grid, 256>>>(
                hs + (long long)(st - 1) * BF, W_hh, b_hh, nullptr,
                u + (long long)st * BF, hs + (long long)st * BF, BSZ, NF, NF);
        }
    }

    // autoencoder over all T*B rows (BN folded into scale/bias)
    {
        dim3 grid1((HID + GBN - 1) / GBN, (TT * BSZ) / GBM);
        gemm_kernel<true, false, false><<<grid1, 256>>>(hs, W1, d1, a1, nullptr, z1, TT * BSZ, HID, NF);
        gemm_kernel<true, false, false><<<grid1, 256>>>(z1, W2, d2, a2, nullptr, z2, TT * BSZ, HID, HID);
        dim3 grid3(NF / GBN, (TT * BSZ) / GBM);
        gemm_kernel<true, false, false><<<grid3, 256>>>(z2, W3, d3, a3, nullptr, y, TT * BSZ, NF, HID);
    }

    loss1_kernel<<<2048, 256>>>();

    // decoder: 16 steps
    {
        const float* hprev = hs + (long long)(TT - 1) * BF;
        const float* xprev = y + (long long)(TT - 1) * BF;
        dim3 gridc(NF / GBN, BSZ / GBM);            // 512x512 cell gemms
        dim3 gridh((HID + GBN - 1) / GBN, BSZ / GBM);
        for (int g = 0; g < MAXG; g++) {
            float* hnew = hd + (g & 1) * BF;
            gemm_kernel<false, false, false><<<gridc, 256>>>(
                xprev, W_ih, b_ih, nullptr, nullptr, ud, BSZ, NF, NF);
            gemm_kernel<false, true, true><<<gridc, 256>>>(
                hprev, W_hh, b_hh, nullptr, ud, hnew, BSZ, NF, NF);
            gemm_kernel<true, false, false><<<gridh, 256>>>(hnew, W1, d1, a1, nullptr, dz1, BSZ, HID, NF);
            gemm_kernel<true, false, false><<<gridh, 256>>>(dz1,  W2, d2, a2, nullptr, dz2, BSZ, HID, HID);
            float* xnew = xall + (long long)g * BF;
            gemm_kernel<true, false, false><<<gridc, 256>>>(dz2,  W3, d3, a3, nullptr, xnew, BSZ, NF, HID);
            hprev = hnew;
            xprev = xnew;
        }
    }

    finalize_kernel<<<BSZ, 256>>>(x, t, out);
    write_loss_kernel<<<1, 1>>>(out, out_size);
}

// round 2
// speedup vs baseline: 1.9523x; 1.9523x over previous
#include <cuda_runtime.h>
#include <cuda_bf16.h>
#include <math.h>

#define BSZ   512
#define TT    64
#define NF    512
#define HID   1000
#define MAXG  16
#define EPSV  1e-5f
#define BF    (BSZ*NF)

// ---------------- scratch -----------------------------------------------------
__device__ float g_xint[TT*BSZ*NF];
__device__ float g_u   [TT*BSZ*NF];
__device__ float g_hs  [TT*BSZ*NF];
__device__ float g_z1  [TT*BSZ*HID];
__device__ float g_z2  [TT*BSZ*HID];
__device__ float g_y   [TT*BSZ*NF];
__device__ float g_xall[MAXG*BSZ*NF];
__device__ float g_dxh [2*BSZ*1024];     // decoder [x|h] buffers
__device__ float g_dz1 [BSZ*HID];
__device__ float g_dz2 [BSZ*HID];
__device__ float g_wc  [512*1024];       // [W_ih | W_hh]
__device__ float g_bc  [512];            // b_ih + b_hh
__device__ float g_a1[HID], g_d1[HID];
__device__ float g_a2[HID], g_d2[HID];
__device__ float g_a3[NF],  g_d3[NF];
__device__ double g_sum1, g_sum2;
__device__ unsigned g_barcnt = 0;
__device__ volatile unsigned g_bargen = 0;

// ---------------- prep --------------------------------------------------------
__global__ void prep_kernel(const float* __restrict__ x,
    const float* W_ih, const float* W_hh, const float* b_ih, const float* b_hh,
    const float* b1, const float* g1, const float* be1, const float* rm1, const float* rv1,
    const float* b2, const float* g2, const float* be2, const float* rm2, const float* rv2,
    const float* b3, const float* g3, const float* be3, const float* rm3, const float* rv3)
{
    long long idx = (long long)blockIdx.x * blockDim.x + threadIdx.x;
    const long long TOT = (long long)TT * BSZ * NF;
    if (idx < TOT) {
        int f = (int)(idx & (NF - 1));
        long long tb = idx >> 9;
        int b = (int)(tb & (BSZ - 1));
        int t = (int)(tb >> 9);
        g_xint[idx] = x[((long long)b * (TT + 1) + t) * NF + f];
    }
    if (idx < 512 * 1024) {
        int n = (int)(idx >> 10), k = (int)(idx & 1023);
        g_wc[idx] = (k < 512) ? W_ih[n * 512 + k] : W_hh[n * 512 + (k - 512)];
    }
    if (idx < HID) {
        float s1 = g1[idx] * rsqrtf(rv1[idx] + EPSV);
        g_a1[idx] = s1;
        g_d1[idx] = s1 * (b1[idx] - rm1[idx]) + be1[idx];
        float s2 = g2[idx] * rsqrtf(rv2[idx] + EPSV);
        g_a2[idx] = s2;
        g_d2[idx] = s2 * (b2[idx] - rm2[idx]) + be2[idx];
    }
    if (idx < NF) {
        float s3 = g3[idx] * rsqrtf(rv3[idx] + EPSV);
        g_a3[idx] = s3;
        g_d3[idx] = s3 * (b3[idx] - rm3[idx]) + be3[idx];
        g_bc[idx] = b_ih[idx] + b_hh[idx];
    }
    if (idx == 0) { g_sum1 = 0.0; g_sum2 = 0.0; g_barcnt = 0; g_bargen = 0; }
}

// ---------------- big GEMM: 128x128x8, 256 thr, 8x8 microtile -----------------
// C[M,N] = f(A[M,*lda] @ W[N,*ldw]^T); M % 128 == 0, K % 8 == 0.
template<bool SCALE, bool TANH>
__global__ void __launch_bounds__(256) gemm128_kernel(
    const float* __restrict__ A, int lda,
    const float* __restrict__ W, int ldw,
    const float* __restrict__ bias, const float* __restrict__ scale,
    float* __restrict__ C, int ldc, int N, int K)
{
    __shared__ float sA[2][8][132];
    __shared__ float sB[2][8][132];

    const int tid = threadIdx.x;
    const int tx = tid & 15, ty = tid >> 4;
    const int m0 = blockIdx.y * 128, n0 = blockIdx.x * 128;

    const int row = tid >> 1, kq = tid & 1;
    const float* Ap = A + (long long)(m0 + row) * lda + kq * 4;
    const int brow = n0 + row;
    const bool bok = brow < N;
    const float* Bp = W + (long long)brow * ldw + kq * 4;

    float acc[8][8];
    #pragma unroll
    for (int i = 0; i < 8; i++)
        #pragma unroll
        for (int j = 0; j < 8; j++) acc[i][j] = 0.0f;

    const int nch = K >> 3;
    float4 pa = *(const float4*)Ap;
    float4 pb = bok ? *(const float4*)Bp : make_float4(0.f, 0.f, 0.f, 0.f);
    {
        sA[0][kq*4+0][row] = pa.x; sA[0][kq*4+1][row] = pa.y;
        sA[0][kq*4+2][row] = pa.z; sA[0][kq*4+3][row] = pa.w;
        sB[0][kq*4+0][row] = pb.x; sB[0][kq*4+1][row] = pb.y;
        sB[0][kq*4+2][row] = pb.z; sB[0][kq*4+3][row] = pb.w;
    }
    __syncthreads();

    for (int c = 0; c < nch; c++) {
        const int buf = c & 1;
        if (c + 1 < nch) {
            pa = *(const float4*)(Ap + (c + 1) * 8);
            pb = bok ? *(const float4*)(Bp + (c + 1) * 8) : make_float4(0.f, 0.f, 0.f, 0.f);
        }
        #pragma unroll
        for (int k = 0; k < 8; k++) {
            float4 a0 = *(const float4*)&sA[buf][k][ty * 4];
            float4 a1 = *(const float4*)&sA[buf][k][64 + ty * 4];
            float4 b0 = *(const float4*)&sB[buf][k][tx * 4];
            float4 b1 = *(const float4*)&sB[buf][k][64 + tx * 4];
            float av[8] = {a0.x, a0.y, a0.z, a0.w, a1.x, a1.y, a1.z, a1.w};
            float bv[8] = {b0.x, b0.y, b0.z, b0.w, b1.x, b1.y, b1.z, b1.w};
            #pragma unroll
            for (int i = 0; i < 8; i++)
                #pragma unroll
                for (int j = 0; j < 8; j++)
                    acc[i][j] += av[i] * bv[j];
        }
        if (c + 1 < nch) {
            const int nb = buf ^ 1;
            sA[nb][kq*4+0][row] = pa.x; sA[nb][kq*4+1][row] = pa.y;
            sA[nb][kq*4+2][row] = pa.z; sA[nb][kq*4+3][row] = pa.w;
            sB[nb][kq*4+0][row] = pb.x; sB[nb][kq*4+1][row] = pb.y;
            sB[nb][kq*4+2][row] = pb.z; sB[nb][kq*4+3][row] = pb.w;
        }
        __syncthreads();
    }

    #pragma unroll
    for (int ih = 0; ih < 2; ih++)
        #pragma unroll
        for (int i = 0; i < 4; i++) {
            int m = m0 + ih * 64 + ty * 4 + i;
            #pragma unroll
            for (int jh = 0; jh < 2; jh++)
                #pragma unroll
                for (int j = 0; j < 4; j++) {
                    int n = n0 + jh * 64 + tx * 4 + j;
                    if (n < N) {
                        float v = acc[ih * 4 + i][jh * 4 + j];
                        if (SCALE) v = v * scale[n] + bias[n];
                        else       v = v + bias[n];
                        if (TANH)  v = tanhf(v);
                        C[(long long)m * ldc + n] = v;
                    }
                }
        }
}

// ---------------- small GEMM: 64x32x16, 256 thr, 4x2 microtile ----------------
template<bool SCALE, bool TANH, bool DUAL>
__global__ void __launch_bounds__(256) gemm64_kernel(
    const float* __restrict__ A, int lda,
    const float* __restrict__ W, int ldw,
    const float* __restrict__ bias, const float* __restrict__ scale,
    float* __restrict__ C, int ldc, float* __restrict__ C2, int ldc2,
    int N, int K)
{
    __shared__ float sA[2][16][68];
    __shared__ float sW[2][16][34];

    const int tid = threadIdx.x;
    const int tx = tid & 15, ty = tid >> 4;
    const int m0 = blockIdx.y * 64, n0 = blockIdx.x * 32;

    const int r = tid >> 2, cq = tid & 3;          // A: 64 rows x 16 k
    const float* Ap = A + (long long)(m0 + r) * lda + cq * 4;
    const int nw = tid >> 3, kw = (tid & 7) * 2;   // W: 32 rows x 16 k
    const int gn = n0 + nw;
    const bool nok = gn < N;
    const float* Wp = W + (long long)gn * ldw + kw;

    float acc[4][2] = {};
    const int nch = (K + 15) >> 4;

    float pa0, pa1, pa2, pa3, pw0, pw1;
    // prefetch chunk 0
    {
        int k = cq * 4;
        if (k + 3 < K) { float4 v = *(const float4*)Ap; pa0=v.x; pa1=v.y; pa2=v.z; pa3=v.w; }
        else { pa0 = (k   < K) ? Ap[0] : 0.f; pa1 = (k+1 < K) ? Ap[1] : 0.f;
               pa2 = (k+2 < K) ? Ap[2] : 0.f; pa3 = (k+3 < K) ? Ap[3] : 0.f; }
        int kk = kw;
        if (nok && kk + 1 < K) { float2 v = *(const float2*)Wp; pw0 = v.x; pw1 = v.y; }
        else { pw0 = (nok && kk < K) ? Wp[0] : 0.f; pw1 = (nok && kk+1 < K) ? Wp[1] : 0.f; }
    }
    {
        float* d = &sA[0][cq*4][r];
        d[0] = pa0; d[68] = pa1; d[136] = pa2; d[204] = pa3;
        sW[0][kw][nw] = pw0; sW[0][kw+1][nw] = pw1;
    }
    __syncthreads();

    for (int c = 0; c < nch; c++) {
        const int buf = c & 1;
        if (c + 1 < nch) {
            int kk = (c + 1) * 16;
            int k = kk + cq * 4;
            if (k + 3 < K) { float4 v = *(const float4*)(Ap + kk); pa0=v.x; pa1=v.y; pa2=v.z; pa3=v.w; }
            else { pa0 = (k   < K) ? Ap[kk+0] : 0.f; pa1 = (k+1 < K) ? Ap[kk+1] : 0.f;
                   pa2 = (k+2 < K) ? Ap[kk+2] : 0.f; pa3 = (k+3 < K) ? Ap[kk+3] : 0.f; }
            int kwg = kk + kw;
            if (nok && kwg + 1 < K) { float2 v = *(const float2*)(Wp + kk); pw0 = v.x; pw1 = v.y; }
            else { pw0 = (nok && kwg < K) ? Wp[kk] : 0.f; pw1 = (nok && kwg+1 < K) ? Wp[kk+1] : 0.f; }
        }
        #pragma unroll
        for (int k = 0; k < 16; k++) {
            float4 a = *(const float4*)&sA[buf][k][ty * 4];
            float2 w = *(const float2*)&sW[buf][k][tx * 2];
            acc[0][0] += a.x * w.x; acc[0][1] += a.x * w.y;
            acc[1][0] += a.y * w.x; acc[1][1] += a.y * w.y;
            acc[2][0] += a.z * w.x; acc[2][1] += a.z * w.y;
            acc[3][0] += a.w * w.x; acc[3][1] += a.w * w.y;
        }
        if (c + 1 < nch) {
            const int nb = buf ^ 1;
            float* d = &sA[nb][cq*4][r];
            d[0] = pa0; d[68] = pa1; d[136] = pa2; d[204] = pa3;
            sW[nb][kw][nw] = pw0; sW[nb][kw+1][nw] = pw1;
        }
        __syncthreads();
    }

    #pragma unroll
    for (int i = 0; i < 4; i++) {
        int m = m0 + ty * 4 + i;
        #pragma unroll
        for (int j = 0; j < 2; j++) {
            int n = n0 + tx * 2 + j;
            if (n < N) {
                float v = acc[i][j];
                if (SCALE) v = v * scale[n] + bias[n];
                else       v = v + bias[n];
                if (TANH)  v = tanhf(v);
                C[(long long)m * ldc + n] = v;
                if (DUAL) C2[(long long)m * ldc2 + n] = v;
            }
        }
    }
}

// ---------------- persistent scan kernel --------------------------------------
__device__ __forceinline__ void grid_barrier(int nb)
{
    __syncthreads();
    if (threadIdx.x == 0) {
        __threadfence();
        unsigned gen = g_bargen;
        if (atomicAdd(&g_barcnt, 1u) == (unsigned)(nb - 1)) {
            g_barcnt = 0;
            __threadfence();
            g_bargen = gen + 1;
        } else {
            while (g_bargen == gen) { }
        }
    }
    __syncthreads();
}

// grid = 128 blocks (8 m-tiles x 16 n-tiles), W_hh tile persistent in SMEM.
__global__ void __launch_bounds__(256) scan_kernel(const float* __restrict__ Whh,
                                                   const float* __restrict__ bhh)
{
    extern __shared__ float sm[];
    float* sW = sm;               // [512][34]
    float* sA = sm + 512 * 34;    // [2][16][68]

    const int tid = threadIdx.x;
    const int tx = tid & 15, ty = tid >> 4;
    const int n0 = (blockIdx.x & 15) * 32;
    const int m0 = (blockIdx.x >> 4) * 64;

    for (int idx = tid; idx < 32 * 512; idx += 256) {
        int k = idx & 511, n = idx >> 9;
        sW[k * 34 + n] = Whh[(n0 + n) * 512 + k];
    }
    const float bh0 = bhh[n0 + tx * 2];
    const float bh1 = bhh[n0 + tx * 2 + 1];
    __syncthreads();

    const int r = tid >> 2, cq = tid & 3;

    for (int t = 0; t < TT; t++) {
        float acc[4][2] = {};
        if (t > 0) {
            const float* A = g_hs + (long long)(t - 1) * BF + (long long)(m0 + r) * 512 + cq * 4;
            float4 pa = *(const float4*)A;
            {
                float* d = sA + (cq * 4) * 68 + r;
                d[0] = pa.x; d[68] = pa.y; d[136] = pa.z; d[204] = pa.w;
            }
            __syncthreads();
            for (int c = 0; c < 32; c++) {
                const int buf = c & 1;
                if (c + 1 < 32) pa = *(const float4*)(A + (c + 1) * 16);
                const float* bA = sA + buf * 1088;
                const float* bW = sW + (c * 16) * 34 + tx * 2;
                #pragma unroll
                for (int k = 0; k < 16; k++) {
                    float4 a = *(const float4*)(bA + k * 68 + ty * 4);
                    float2 w = *(const float2*)(bW + k * 34);
                    acc[0][0] += a.x * w.x; acc[0][1] += a.x * w.y;
                    acc[1][0] += a.y * w.x; acc[1][1] += a.y * w.y;
                    acc[2][0] += a.z * w.x; acc[2][1] += a.z * w.y;
                    acc[3][0] += a.w * w.x; acc[3][1] += a.w * w.y;
                }
                if (c + 1 < 32) {
                    float* d = sA + (buf ^ 1) * 1088 + (cq * 4) * 68 + r;
                    d[0] = pa.x; d[68] = pa.y; d[136] = pa.z; d[204] = pa.w;
                }
                __syncthreads();
            }
        }
        const float* Ut = g_u + (long long)t * BF;
        float* Ht = g_hs + (long long)t * BF;
        #pragma unroll
        for (int i = 0; i < 4; i++) {
            long long off = (long long)(m0 + ty * 4 + i) * 512 + n0 + tx * 2;
            float2 u = *(const float2*)(Ut + off);
            float2 h;
            h.x = tanhf(acc[i][0] + u.x + bh0);
            h.y = tanhf(acc[i][1] + u.y + bh1);
            *(float2*)(Ht + off) = h;
        }
        grid_barrier(gridDim.x);
    }
}

// ---------------- reductions / misc -------------------------------------------
__device__ __forceinline__ double block_reduce(double v)
{
    __shared__ double sh[32];
    #pragma unroll
    for (int o = 16; o > 0; o >>= 1) v += __shfl_down_sync(0xffffffffu, v, o);
    int lane = threadIdx.x & 31, w = threadIdx.x >> 5;
    if (lane == 0) sh[w] = v;
    __syncthreads();
    if (w == 0) {
        int nw = (blockDim.x + 31) >> 5;
        v = (lane < nw) ? sh[lane] : 0.0;
        #pragma unroll
        for (int o = 16; o > 0; o >>= 1) v += __shfl_down_sync(0xffffffffu, v, o);
    }
    return v;
}

__global__ void loss1_kernel()
{
    const long long TOT = (long long)(TT - 1) * BSZ * NF;
    double local = 0.0;
    for (long long idx = (long long)blockIdx.x * blockDim.x + threadIdx.x;
         idx < TOT; idx += (long long)gridDim.x * blockDim.x) {
        float d = g_y[idx] - g_xint[idx + BF];
        local += (double)d * (double)d;
    }
    double s = block_reduce(local);
    if (threadIdx.x == 0) atomicAdd(&g_sum1, s);
}

__global__ void init_dec_kernel()
{
    int idx = blockIdx.x * blockDim.x + threadIdx.x;
    if (idx < BF) {
        int b = idx >> 9, f = idx & 511;
        g_dxh[(long long)b * 1024 + f]       = g_y [(long long)63 * BF + idx];
        g_dxh[(long long)b * 1024 + 512 + f] = g_hs[(long long)63 * BF + idx];
    }
}

__global__ void finalize_kernel(const float* __restrict__ x,
                                const int* __restrict__ t,
                                float* __restrict__ out)
{
    int b = blockIdx.x;
    int g = t[b] - 1;
    const float* xp = g_xall + ((long long)g * BSZ + b) * NF;
    const float* xf = x + ((long long)b * (TT + 1) + TT) * NF;
    double local = 0.0;
    for (int f = threadIdx.x; f < NF; f += blockDim.x) {
        float v = xp[f];
        out[(long long)b * NF + f] = v;
        float d = v - xf[f];
        local += (double)d * (double)d;
    }
    double s = block_reduce(local);
    if (threadIdx.x == 0) atomicAdd(&g_sum2, s);
}

__global__ void write_loss_kernel(float* __restrict__ out, int out_size)
{
    if (out_size > BSZ * NF) {
        double n1 = (double)(TT - 1) * BSZ * NF;
        double n2 = (double)BSZ * NF;
        double loss = g_sum1 / (n1 * n1) + g_sum2 / (n2 * n2);
        out[BSZ * NF] = (float)loss;
    }
}

// ---------------- launch -------------------------------------------------------
extern "C" void kernel_launch(void* const* d_in, const int* in_sizes, int n_in,
                              void* d_out, int out_size)
{
    const float* x    = (const float*)d_in[0];
    const int*   t    = (const int*)  d_in[1];
    const float* W_ih = (const float*)d_in[2];
    const float* W_hh = (const float*)d_in[3];
    const float* b_ih = (const float*)d_in[4];
    const float* b_hh = (const float*)d_in[5];
    const float* W1   = (const float*)d_in[6];
    const float* b1   = (const float*)d_in[7];
    const float* g1   = (const float*)d_in[8];
    const float* be1  = (const float*)d_in[9];
    const float* rm1  = (const float*)d_in[10];
    const float* rv1  = (const float*)d_in[11];
    const float* W2   = (const float*)d_in[12];
    const float* b2   = (const float*)d_in[13];
    const float* g2   = (const float*)d_in[14];
    const float* be2  = (const float*)d_in[15];
    const float* rm2  = (const float*)d_in[16];
    const float* rv2  = (const float*)d_in[17];
    const float* W3   = (const float*)d_in[18];
    const float* b3   = (const float*)d_in[19];
    const float* g3   = (const float*)d_in[20];
    const float* be3  = (const float*)d_in[21];
    const float* rm3  = (const float*)d_in[22];
    const float* rv3  = (const float*)d_in[23];
    float* out = (float*)d_out;

    float *xint, *u, *hs, *z1, *z2, *y, *xall, *dxh, *dz1, *dz2, *wc, *bc;
    float *a1, *d1, *a2, *d2, *a3, *d3;
    cudaGetSymbolAddress((void**)&xint, g_xint);
    cudaGetSymbolAddress((void**)&u,    g_u);
    cudaGetSymbolAddress((void**)&hs,   g_hs);
    cudaGetSymbolAddress((void**)&z1,   g_z1);
    cudaGetSymbolAddress((void**)&z2,   g_z2);
    cudaGetSymbolAddress((void**)&y,    g_y);
    cudaGetSymbolAddress((void**)&xall, g_xall);
    cudaGetSymbolAddress((void**)&dxh,  g_dxh);
    cudaGetSymbolAddress((void**)&dz1,  g_dz1);
    cudaGetSymbolAddress((void**)&dz2,  g_dz2);
    cudaGetSymbolAddress((void**)&wc,   g_wc);
    cudaGetSymbolAddress((void**)&bc,   g_bc);
    cudaGetSymbolAddress((void**)&a1,   g_a1);
    cudaGetSymbolAddress((void**)&d1,   g_d1);
    cudaGetSymbolAddress((void**)&a2,   g_a2);
    cudaGetSymbolAddress((void**)&d2,   g_d2);
    cudaGetSymbolAddress((void**)&a3,   g_a3);
    cudaGetSymbolAddress((void**)&d3,   g_d3);

    const int scan_smem = (512 * 34 + 2 * 16 * 68) * 4;   // 78336 B
    cudaFuncSetAttribute(scan_kernel,
                         cudaFuncAttributeMaxDynamicSharedMemorySize, scan_smem);

    const long long TOT = (long long)TT * BSZ * NF;
    prep_kernel<<<(unsigned)((TOT + 255) / 256), 256>>>(
        x, W_ih, W_hh, b_ih, b_hh,
        b1, g1, be1, rm1, rv1, b2, g2, be2, rm2, rv2, b3, g3, be3, rm3, rv3);

    // U = XIN @ W_ih^T + b_ih over all T*B rows
    {
        dim3 grid(NF / 128, (TT * BSZ) / 128);
        gemm128_kernel<false, false><<<grid, 256>>>(
            xint, NF, W_ih, NF, b_ih, nullptr, u, NF, NF, NF);
    }

    // persistent scan
    scan_kernel<<<128, 256, scan_smem>>>(W_hh, b_hh);

    // autoencoder over all rows
    {
        dim3 grid1((HID + 127) / 128, (TT * BSZ) / 128);
        gemm128_kernel<true, false><<<grid1, 256>>>(hs, NF,  W1, NF,  d1, a1, z1, HID, HID, NF);
        gemm128_kernel<true, false><<<grid1, 256>>>(z1, HID, W2, HID, d2, a2, z2, HID, HID, HID);
        dim3 grid3(NF / 128, (TT * BSZ) / 128);
        gemm128_kernel<true, false><<<grid3, 256>>>(z2, HID, W3, HID, d3, a3, y,  NF,  NF,  HID);
    }

    loss1_kernel<<<2048, 256>>>();
    init_dec_kernel<<<(BF + 255) / 256, 256>>>();

    // decoder: 16 steps x 4 fused GEMMs
    {
        dim3 gcell(512 / 32, BSZ / 64);                       // (16, 8)
        dim3 ghid((HID + 31) / 32, BSZ / 64);                 // (32, 8)
        for (int g = 0; g < MAXG; g++) {
            float* cur  = dxh + (size_t)(g & 1) * BSZ * 1024;
            float* next = dxh + (size_t)((g + 1) & 1) * BSZ * 1024;
            // h' = tanh([x|h] @ Wc^T + bc)
            gemm64_kernel<false, true, false><<<gcell, 256>>>(
                cur, 1024, wc, 1024, bc, nullptr, next + 512, 1024, nullptr, 0, 512, 1024);
            gemm64_kernel<true, false, false><<<ghid, 256>>>(
                next + 512, 1024, W1, NF, d1, a1, dz1, HID, nullptr, 0, HID, NF);
            gemm64_kernel<true, false, false><<<ghid, 256>>>(
                dz1, HID, W2, HID, d2, a2, dz2, HID, nullptr, 0, HID, HID);
            gemm64_kernel<true, false, true><<<gcell, 256>>>(
                dz2, HID, W3, HID, d3, a3, next, 1024,
                xall + (size_t)g * BF, NF, 512, HID);
        }
    }

    finalize_kernel<<<BSZ, 256>>>(x, t, out);
    write_loss_kernel<<<1, 1>>>(out, out_size);
}

// round 3
// speedup vs baseline: 2.4462x; 1.2530x over previous
#include <cuda_runtime.h>
#include <cuda_bf16.h>
#include <math.h>

#define BSZ   512
#define TT    64
#define NF    512
#define HID   1000
#define MAXG  16
#define EPSV  1e-5f
#define BF    (BSZ*NF)

// ---------------- scratch -----------------------------------------------------
__device__ float g_xint[TT*BSZ*NF];
__device__ float g_u   [TT*BSZ*NF];
__device__ float g_hs  [TT*BSZ*NF];
__device__ float g_z1  [TT*BSZ*HID];
__device__ float g_z2  [TT*BSZ*HID];
__device__ float g_y   [TT*BSZ*NF];
__device__ float g_xall[MAXG*BSZ*NF];
__device__ float g_dxh [2*BSZ*1024];
__device__ float g_dz1 [BSZ*HID];
__device__ float g_dz2 [BSZ*HID];
__device__ float g_wc  [512*1024];
__device__ float g_bc  [512];
__device__ float g_a1[HID], g_d1[HID];
__device__ float g_a2[HID], g_d2[HID];
__device__ float g_a3[NF],  g_d3[NF];
__device__ double g_sum1, g_sum2;
__device__ unsigned g_barcnt = 0;
__device__ volatile unsigned g_bargen = 0;

// ---------------- helpers ------------------------------------------------------
__device__ __forceinline__ unsigned f2tf(float f)
{
    unsigned r;
    asm("cvt.rna.tf32.f32 %0, %1;" : "=r"(r) : "f"(f));
    return r;
}

__device__ __forceinline__ void mma_tf32(float* c, const unsigned* a, const unsigned* b)
{
    asm volatile(
        "mma.sync.aligned.m16n8k8.row.col.f32.tf32.tf32.f32 "
        "{%0,%1,%2,%3},{%4,%5,%6,%7},{%8,%9},{%0,%1,%2,%3};"
        : "+f"(c[0]), "+f"(c[1]), "+f"(c[2]), "+f"(c[3])
        : "r"(a[0]), "r"(a[1]), "r"(a[2]), "r"(a[3]), "r"(b[0]), "r"(b[1]));
}

// ---------------- prep ---------------------------------------------------------
__global__ void prep_kernel(const float* __restrict__ x,
    const float* W_ih, const float* W_hh, const float* b_ih, const float* b_hh,
    const float* b1, const float* g1, const float* be1, const float* rm1, const float* rv1,
    const float* b2, const float* g2, const float* be2, const float* rm2, const float* rv2,
    const float* b3, const float* g3, const float* be3, const float* rm3, const float* rv3)
{
    long long idx = (long long)blockIdx.x * blockDim.x + threadIdx.x;
    const long long TOT = (long long)TT * BSZ * NF;
    if (idx < TOT) {
        int f = (int)(idx & (NF - 1));
        long long tb = idx >> 9;
        int b = (int)(tb & (BSZ - 1));
        int t = (int)(tb >> 9);
        g_xint[idx] = x[((long long)b * (TT + 1) + t) * NF + f];
    }
    if (idx < 512 * 1024) {
        int n = (int)(idx >> 10), k = (int)(idx & 1023);
        g_wc[idx] = (k < 512) ? W_ih[n * 512 + k] : W_hh[n * 512 + (k - 512)];
    }
    if (idx < HID) {
        float s1 = g1[idx] * rsqrtf(rv1[idx] + EPSV);
        g_a1[idx] = s1;
        g_d1[idx] = s1 * (b1[idx] - rm1[idx]) + be1[idx];
        float s2 = g2[idx] * rsqrtf(rv2[idx] + EPSV);
        g_a2[idx] = s2;
        g_d2[idx] = s2 * (b2[idx] - rm2[idx]) + be2[idx];
    }
    if (idx < NF) {
        float s3 = g3[idx] * rsqrtf(rv3[idx] + EPSV);
        g_a3[idx] = s3;
        g_d3[idx] = s3 * (b3[idx] - rm3[idx]) + be3[idx];
        g_bc[idx] = b_ih[idx] + b_hh[idx];
    }
    if (idx == 0) { g_sum1 = 0.0; g_sum2 = 0.0; g_barcnt = 0; g_bargen = 0; }
}

// ---------------- tf32 tensor-core GEMM ----------------------------------------
// C[M,N] = f(A[M,lda] @ W[N,ldw]^T). BM=BN=THREADS/2. BK=16.
// Warp grid WM x WN; warp tile (BM/WM) x (BN/WN); frags m16n8k8.
template<int BM, int BN, int WM, int WN, bool SCALE, bool TANH, bool DUAL>
__global__ void __launch_bounds__(WM*WN*32) mma_gemm_kernel(
    const float* __restrict__ A, int lda,
    const float* __restrict__ W, int ldw,
    const float* __restrict__ bias, const float* __restrict__ scale,
    float* __restrict__ C, int ldc, float* __restrict__ C2, int ldc2,
    int N, int K)
{
    constexpr int THREADS = WM * WN * 32;
    constexpr int TM = BM / WM;          // 64
    constexpr int TN = BN / WN;          // 32 or 16
    constexpr int FM = TM / 16;          // 4
    constexpr int FN = TN / 8;           // 4 or 2
    constexpr int PAD = 4;

    __shared__ unsigned sA[2][16][BM + PAD];
    __shared__ unsigned sB[2][16][BN + PAD];

    const int tid  = threadIdx.x;
    const int lane = tid & 31;
    const int wid  = tid >> 5;
    const int wm   = wid / WN, wn = wid % WN;
    const int g8   = lane >> 2, t4 = lane & 3;

    const int m0 = blockIdx.y * BM;
    const int n0 = blockIdx.x * BN;

    // staging: 2 threads per row; each thread covers 8 consecutive k
    const int srow = tid >> 1;
    const int skq  = (tid & 1) * 8;
    const float* Ap = A + (long long)(m0 + srow) * lda + skq;
    const int brow = n0 + srow;
    const bool bok = brow < N;
    const float* Bp = W + (long long)brow * ldw + skq;

    float acc[FM][FN][4];
    #pragma unroll
    for (int i = 0; i < FM; i++)
        #pragma unroll
        for (int j = 0; j < FN; j++)
            #pragma unroll
            for (int q = 0; q < 4; q++) acc[i][j][q] = 0.0f;

    const int nch = (K + 15) >> 4;

    float pa[8], pb[8];
    // prefetch chunk 0
    {
        if (16 <= K) {
            float4 v0 = *(const float4*)Ap, v1 = *(const float4*)(Ap + 4);
            pa[0]=v0.x; pa[1]=v0.y; pa[2]=v0.z; pa[3]=v0.w;
            pa[4]=v1.x; pa[5]=v1.y; pa[6]=v1.z; pa[7]=v1.w;
            if (bok) {
                float4 w0 = *(const float4*)Bp, w1 = *(const float4*)(Bp + 4);
                pb[0]=w0.x; pb[1]=w0.y; pb[2]=w0.z; pb[3]=w0.w;
                pb[4]=w1.x; pb[5]=w1.y; pb[6]=w1.z; pb[7]=w1.w;
            } else {
                #pragma unroll
                for (int q = 0; q < 8; q++) pb[q] = 0.0f;
            }
        } else {
            #pragma unroll
            for (int q = 0; q < 8; q++) {
                int k = skq + q;
                pa[q] = (k < K) ? Ap[q] : 0.0f;
                pb[q] = (bok && k < K) ? Bp[q] : 0.0f;
            }
        }
    }
    #pragma unroll
    for (int q = 0; q < 8; q++) {
        sA[0][skq + q][srow] = f2tf(pa[q]);
        sB[0][skq + q][srow] = f2tf(pb[q]);
    }
    __syncthreads();

    for (int c = 0; c < nch; c++) {
        const int buf = c & 1;
        if (c + 1 < nch) {
            const int kk = (c + 1) * 16;
            if (kk + 16 <= K) {
                float4 v0 = *(const float4*)(Ap + kk), v1 = *(const float4*)(Ap + kk + 4);
                pa[0]=v0.x; pa[1]=v0.y; pa[2]=v0.z; pa[3]=v0.w;
                pa[4]=v1.x; pa[5]=v1.y; pa[6]=v1.z; pa[7]=v1.w;
                if (bok) {
                    float4 w0 = *(const float4*)(Bp + kk), w1 = *(const float4*)(Bp + kk + 4);
                    pb[0]=w0.x; pb[1]=w0.y; pb[2]=w0.z; pb[3]=w0.w;
                    pb[4]=w1.x; pb[5]=w1.y; pb[6]=w1.z; pb[7]=w1.w;
                } else {
                    #pragma unroll
                    for (int q = 0; q < 8; q++) pb[q] = 0.0f;
                }
            } else {
                #pragma unroll
                for (int q = 0; q < 8; q++) {
                    int k = kk + skq + q;
                    pa[q] = (k < K) ? Ap[kk + q] : 0.0f;
                    pb[q] = (bok && k < K) ? Bp[kk + q] : 0.0f;
                }
            }
        }

        #pragma unroll
        for (int ks = 0; ks < 16; ks += 8) {
            unsigned af[FM][4], bf[FN][2];
            #pragma unroll
            for (int i = 0; i < FM; i++) {
                int m = wm * TM + 16 * i + g8;
                af[i][0] = sA[buf][ks + t4][m];
                af[i][1] = sA[buf][ks + t4][m + 8];
                af[i][2] = sA[buf][ks + t4 + 4][m];
                af[i][3] = sA[buf][ks + t4 + 4][m + 8];
            }
            #pragma unroll
            for (int j = 0; j < FN; j++) {
                int n = wn * TN + 8 * j + g8;
                bf[j][0] = sB[buf][ks + t4][n];
                bf[j][1] = sB[buf][ks + t4 + 4][n];
            }
            #pragma unroll
            for (int i = 0; i < FM; i++)
                #pragma unroll
                for (int j = 0; j < FN; j++)
                    mma_tf32(acc[i][j], af[i], bf[j]);
        }

        if (c + 1 < nch) {
            const int nb = buf ^ 1;
            #pragma unroll
            for (int q = 0; q < 8; q++) {
                sA[nb][skq + q][srow] = f2tf(pa[q]);
                sB[nb][skq + q][srow] = f2tf(pb[q]);
            }
        }
        __syncthreads();
    }

    // epilogue
    #pragma unroll
    for (int i = 0; i < FM; i++) {
        int row = m0 + wm * TM + 16 * i + g8;
        #pragma unroll
        for (int j = 0; j < FN; j++) {
            int col = n0 + wn * TN + 8 * j + 2 * t4;
            if (col < N) {
                float2 bi = *(const float2*)(bias + col);
                float2 sc;
                if (SCALE) sc = *(const float2*)(scale + col);
                float v00 = acc[i][j][0], v01 = acc[i][j][1];
                float v10 = acc[i][j][2], v11 = acc[i][j][3];
                if (SCALE) {
                    v00 = v00 * sc.x + bi.x; v01 = v01 * sc.y + bi.y;
                    v10 = v10 * sc.x + bi.x; v11 = v11 * sc.y + bi.y;
                } else {
                    v00 += bi.x; v01 += bi.y; v10 += bi.x; v11 += bi.y;
                }
                if (TANH) { v00 = tanhf(v00); v01 = tanhf(v01);
                            v10 = tanhf(v10); v11 = tanhf(v11); }
                *(float2*)(C + (long long)row * ldc + col)       = make_float2(v00, v01);
                *(float2*)(C + (long long)(row + 8) * ldc + col) = make_float2(v10, v11);
                if (DUAL) {
                    *(float2*)(C2 + (long long)row * ldc2 + col)       = make_float2(v00, v01);
                    *(float2*)(C2 + (long long)(row + 8) * ldc2 + col) = make_float2(v10, v11);
                }
            }
        }
    }
}

// ---------------- persistent scan kernel (FFMA) --------------------------------
__device__ __forceinline__ void grid_barrier(int nb)
{
    __syncthreads();
    if (threadIdx.x == 0) {
        __threadfence();
        unsigned gen = g_bargen;
        if (atomicAdd(&g_barcnt, 1u) == (unsigned)(nb - 1)) {
            g_barcnt = 0;
            __threadfence();
            g_bargen = gen + 1;
        } else {
            while (g_bargen == gen) { }
        }
    }
    __syncthreads();
}

__global__ void __launch_bounds__(256) scan_kernel(const float* __restrict__ Whh,
                                                   const float* __restrict__ bhh)
{
    extern __shared__ float sm[];
    float* sW = sm;               // [512][34]
    float* sA = sm + 512 * 34;    // [2][16][68]

    const int tid = threadIdx.x;
    const int tx = tid & 15, ty = tid >> 4;
    const int n0 = (blockIdx.x & 15) * 32;
    const int m0 = (blockIdx.x >> 4) * 64;

    for (int idx = tid; idx < 32 * 512; idx += 256) {
        int k = idx & 511, n = idx >> 9;
        sW[k * 34 + n] = Whh[(n0 + n) * 512 + k];
    }
    const float bh0 = bhh[n0 + tx * 2];
    const float bh1 = bhh[n0 + tx * 2 + 1];
    __syncthreads();

    const int r = tid >> 2, cq = tid & 3;

    for (int t = 0; t < TT; t++) {
        float acc[4][2] = {};
        if (t > 0) {
            const float* A = g_hs + (long long)(t - 1) * BF + (long long)(m0 + r) * 512 + cq * 4;
            float4 pa = *(const float4*)A;
            {
                float* d = sA + (cq * 4) * 68 + r;
                d[0] = pa.x; d[68] = pa.y; d[136] = pa.z; d[204] = pa.w;
            }
            __syncthreads();
            for (int c = 0; c < 32; c++) {
                const int buf = c & 1;
                if (c + 1 < 32) pa = *(const float4*)(A + (c + 1) * 16);
                const float* bA = sA + buf * 1088;
                const float* bW = sW + (c * 16) * 34 + tx * 2;
                #pragma unroll
                for (int k = 0; k < 16; k++) {
                    float4 a = *(const float4*)(bA + k * 68 + ty * 4);
                    float2 w = *(const float2*)(bW + k * 34);
                    acc[0][0] += a.x * w.x; acc[0][1] += a.x * w.y;
                    acc[1][0] += a.y * w.x; acc[1][1] += a.y * w.y;
                    acc[2][0] += a.z * w.x; acc[2][1] += a.z * w.y;
                    acc[3][0] += a.w * w.x; acc[3][1] += a.w * w.y;
                }
                if (c + 1 < 32) {
                    float* d = sA + (buf ^ 1) * 1088 + (cq * 4) * 68 + r;
                    d[0] = pa.x; d[68] = pa.y; d[136] = pa.z; d[204] = pa.w;
                }
                __syncthreads();
            }
        }
        const float* Ut = g_u + (long long)t * BF;
        float* Ht = g_hs + (long long)t * BF;
        #pragma unroll
        for (int i = 0; i < 4; i++) {
            long long off = (long long)(m0 + ty * 4 + i) * 512 + n0 + tx * 2;
            float2 u = *(const float2*)(Ut + off);
            float2 h;
            h.x = tanhf(acc[i][0] + u.x + bh0);
            h.y = tanhf(acc[i][1] + u.y + bh1);
            *(float2*)(Ht + off) = h;
        }
        grid_barrier(gridDim.x);
    }
}

// ---------------- reductions / misc --------------------------------------------
__device__ __forceinline__ double block_reduce(double v)
{
    __shared__ double sh[32];
    #pragma unroll
    for (int o = 16; o > 0; o >>= 1) v += __shfl_down_sync(0xffffffffu, v, o);
    int lane = threadIdx.x & 31, w = threadIdx.x >> 5;
    if (lane == 0) sh[w] = v;
    __syncthreads();
    if (w == 0) {
        int nw = (blockDim.x + 31) >> 5;
        v = (lane < nw) ? sh[lane] : 0.0;
        #pragma unroll
        for (int o = 16; o > 0; o >>= 1) v += __shfl_down_sync(0xffffffffu, v, o);
    }
    return v;
}

__global__ void loss1_kernel()
{
    const long long TOT = (long long)(TT - 1) * BSZ * NF;
    double local = 0.0;
    for (long long idx = (long long)blockIdx.x * blockDim.x + threadIdx.x;
         idx < TOT; idx += (long long)gridDim.x * blockDim.x) {
        float d = g_y[idx] - g_xint[idx + BF];
        local += (double)d * (double)d;
    }
    double s = block_reduce(local);
    if (threadIdx.x == 0) atomicAdd(&g_sum1, s);
}

__global__ void init_dec_kernel()
{
    int idx = blockIdx.x * blockDim.x + threadIdx.x;
    if (idx < BF) {
        int b = idx >> 9, f = idx & 511;
        g_dxh[(long long)b * 1024 + f]       = g_y [(long long)63 * BF + idx];
        g_dxh[(long long)b * 1024 + 512 + f] = g_hs[(long long)63 * BF + idx];
    }
}

__global__ void finalize_kernel(const float* __restrict__ x,
                                const int* __restrict__ t,
                                float* __restrict__ out)
{
    int b = blockIdx.x;
    int g = t[b] - 1;
    const float* xp = g_xall + ((long long)g * BSZ + b) * NF;
    const float* xf = x + ((long long)b * (TT + 1) + TT) * NF;
    double local = 0.0;
    for (int f = threadIdx.x; f < NF; f += blockDim.x) {
        float v = xp[f];
        out[(long long)b * NF + f] = v;
        float d = v - xf[f];
        local += (double)d * (double)d;
    }
    double s = block_reduce(local);
    if (threadIdx.x == 0) atomicAdd(&g_sum2, s);
}

__global__ void write_loss_kernel(float* __restrict__ out, int out_size)
{
    if (out_size > BSZ * NF) {
        double n1 = (double)(TT - 1) * BSZ * NF;
        double n2 = (double)BSZ * NF;
        double loss = g_sum1 / (n1 * n1) + g_sum2 / (n2 * n2);
        out[BSZ * NF] = (float)loss;
    }
}

// ---------------- launch --------------------------------------------------------
extern "C" void kernel_launch(void* const* d_in, const int* in_sizes, int n_in,
                              void* d_out, int out_size)
{
    const float* x    = (const float*)d_in[0];
    const int*   t    = (const int*)  d_in[1];
    const float* W_ih = (const float*)d_in[2];
    const float* W_hh = (const float*)d_in[3];
    const float* b_ih = (const float*)d_in[4];
    const float* b_hh = (const float*)d_in[5];
    const float* W1   = (const float*)d_in[6];
    const float* b1   = (const float*)d_in[7];
    const float* g1   = (const float*)d_in[8];
    const float* be1  = (const float*)d_in[9];
    const float* rm1  = (const float*)d_in[10];
    const float* rv1  = (const float*)d_in[11];
    const float* W2   = (const float*)d_in[12];
    const float* b2   = (const float*)d_in[13];
    const float* g2   = (const float*)d_in[14];
    const float* be2  = (const float*)d_in[15];
    const float* rm2  = (const float*)d_in[16];
    const float* rv2  = (const float*)d_in[17];
    const float* W3   = (const float*)d_in[18];
    const float* b3   = (const float*)d_in[19];
    const float* g3   = (const float*)d_in[20];
    const float* be3  = (const float*)d_in[21];
    const float* rm3  = (const float*)d_in[22];
    const float* rv3  = (const float*)d_in[23];
    float* out = (float*)d_out;

    float *xint, *u, *hs, *z1, *z2, *y, *xall, *dxh, *dz1, *dz2, *wc, *bc;
    float *a1, *d1, *a2, *d2, *a3, *d3;
    cudaGetSymbolAddress((void**)&xint, g_xint);
    cudaGetSymbolAddress((void**)&u,    g_u);
    cudaGetSymbolAddress((void**)&hs,   g_hs);
    cudaGetSymbolAddress((void**)&z1,   g_z1);
    cudaGetSymbolAddress((void**)&z2,   g_z2);
    cudaGetSymbolAddress((void**)&y,    g_y);
    cudaGetSymbolAddress((void**)&xall, g_xall);
    cudaGetSymbolAddress((void**)&dxh,  g_dxh);
    cudaGetSymbolAddress((void**)&dz1,  g_dz1);
    cudaGetSymbolAddress((void**)&dz2,  g_dz2);
    cudaGetSymbolAddress((void**)&wc,   g_wc);
    cudaGetSymbolAddress((void**)&bc,   g_bc);
    cudaGetSymbolAddress((void**)&a1,   g_a1);
    cudaGetSymbolAddress((void**)&d1,   g_d1);
    cudaGetSymbolAddress((void**)&a2,   g_a2);
    cudaGetSymbolAddress((void**)&d2,   g_d2);
    cudaGetSymbolAddress((void**)&a3,   g_a3);
    cudaGetSymbolAddress((void**)&d3,   g_d3);

    const int scan_smem = (512 * 34 + 2 * 16 * 68) * 4;
    cudaFuncSetAttribute(scan_kernel,
                         cudaFuncAttributeMaxDynamicSharedMemorySize, scan_smem);

    const long long TOT = (long long)TT * BSZ * NF;
    prep_kernel<<<(unsigned)((TOT + 255) / 256), 256>>>(
        x, W_ih, W_hh, b_ih, b_hh,
        b1, g1, be1, rm1, rv1, b2, g2, be2, rm2, rv2, b3, g3, be3, rm3, rv3);

    // U = XIN @ W_ih^T + b_ih
    {
        dim3 grid(NF / 128, (TT * BSZ) / 128);
        mma_gemm_kernel<128,128,2,4,false,false,false><<<grid, 256>>>(
            xint, NF, W_ih, NF, b_ih, nullptr, u, NF, nullptr, 0, NF, NF);
    }

    // persistent scan
    scan_kernel<<<128, 256, scan_smem>>>(W_hh, b_hh);

    // autoencoder over all rows
    {
        dim3 grid1((HID + 127) / 128, (TT * BSZ) / 128);
        mma_gemm_kernel<128,128,2,4,true,false,false><<<grid1, 256>>>(
            hs, NF, W1, NF, d1, a1, z1, HID, nullptr, 0, HID, NF);
        mma_gemm_kernel<128,128,2,4,true,false,false><<<grid1, 256>>>(
            z1, HID, W2, HID, d2, a2, z2, HID, nullptr, 0, HID, HID);
        dim3 grid3(NF / 128, (TT * BSZ) / 128);
        mma_gemm_kernel<128,128,2,4,true,false,false><<<grid3, 256>>>(
            z2, HID, W3, HID, d3, a3, y, NF, nullptr, 0, NF, HID);
    }

    loss1_kernel<<<2048, 256>>>();
    init_dec_kernel<<<(BF + 255) / 256, 256>>>();

    // decoder: 16 steps x 4 mma GEMMs (64x64 blocks, 128 threads)
    {
        dim3 gcell(512 / 64, BSZ / 64);                // (8, 8)
        dim3 ghid((HID + 63) / 64, BSZ / 64);          // (16, 8)
        for (int g = 0; g < MAXG; g++) {
            float* cur  = dxh + (size_t)(g & 1) * BSZ * 1024;
            float* next = dxh + (size_t)((g + 1) & 1) * BSZ * 1024;
            mma_gemm_kernel<64,64,1,4,false,true,false><<<gcell, 128>>>(
                cur, 1024, wc, 1024, bc, nullptr, next + 512, 1024, nullptr, 0, 512, 1024);
            mma_gemm_kernel<64,64,1,4,true,false,false><<<ghid, 128>>>(
                next + 512, 1024, W1, NF, d1, a1, dz1, HID, nullptr, 0, HID, NF);
            mma_gemm_kernel<64,64,1,4,true,false,false><<<ghid, 128>>>(
                dz1, HID, W2, HID, d2, a2, dz2, HID, nullptr, 0, HID, HID);
            mma_gemm_kernel<64,64,1,4,true,false,true><<<gcell, 128>>>(
                dz2, HID, W3, HID, d3, a3, next, 1024,
                xall + (size_t)g * BF, NF, 512, HID);
        }
    }

    finalize_kernel<<<BSZ, 256>>>(x, t, out);
    write_loss_kernel<<<1, 1>>>(out, out_size);
}